// round 13
// baseline (speedup 1.0000x reference)
#include <cuda_runtime.h>
#include <cuda_bf16.h>

typedef unsigned long long u64;
typedef unsigned int u32;

#define NB 64
#define NS 100
#define NQ 129
#define DD 128

// -------------------- device scratch ---------------------------------------
__device__ __align__(16) float g_AL [NB*NS*DD];
__device__ __align__(16) float g_G23[NB*NS*2*DD];
__device__ __align__(16) float g_UIT[NB*NS*DD];
__device__ __align__(16) float g_HT [NB*NS*DD];
__device__ __align__(16) float g_W5T [DD*2*DD];   // [f][k]
__device__ __align__(16) float g_w1s [DD];
__device__ __align__(16) float g_QS  [NB*NS];

__device__ __forceinline__ float sigm(float x) {
    return __fdividef(1.f, 1.f + __expf(-x));
}
#define FMA2(d, a, bb) asm("fma.rn.f32x2 %0, %1, %2, %0;" : "+l"(d) : "l"(a), "l"(bb))
__device__ __forceinline__ float2 unpk(u64 v) {
    float2 r;
    asm("mov.b64 {%0, %1}, %2;" : "=f"(r.x), "=f"(r.y) : "l"(v));
    return r;
}
__device__ __forceinline__ u32 smem_u32(const void* p) {
    u32 a;
    asm("{ .reg .u64 t; cvta.to.shared.u64 t, %1; cvt.u32.u64 %0, t; }" : "=r"(a) : "l"(p));
    return a;
}
__device__ __forceinline__ u32 mapa_u32(u32 laddr, u32 r) {
    u32 a;
    asm("mapa.shared::cluster.u32 %0, %1, %2;" : "=r"(a) : "r"(laddr), "r"(r));
    return a;
}
__device__ __forceinline__ void st_cluster_f32(u32 raddr, float v) {
    asm volatile("st.shared::cluster.f32 [%0], %1;" :: "r"(raddr), "f"(v) : "memory");
}
__device__ __forceinline__ void st_async_f32(u32 raddr, float v, u32 rmbar) {
    asm volatile("st.async.shared::cluster.mbarrier::complete_tx::bytes.f32 [%0], %1, [%2];"
                 :: "r"(raddr), "f"(v), "r"(rmbar) : "memory");
}
#define CLUSTER_SYNC() do { \
    asm volatile("barrier.cluster.arrive.aligned;" ::: "memory"); \
    asm volatile("barrier.cluster.wait.aligned;"   ::: "memory"); \
} while (0)
#define MBARRIER_INIT(mb, c) \
    asm volatile("mbarrier.init.shared.b64 [%0], %1;" :: "r"((u32)(mb)), "r"((u32)(c)) : "memory")
#define MBAR_EXPECT_TX(mb, bytes) \
    asm volatile("mbarrier.arrive.expect_tx.shared.b64 _, [%0], %1;" \
                 :: "r"((u32)(mb)), "r"((u32)(bytes)) : "memory")
#define MBAR_WAIT(mb, par) do { \
    u32 _m = (u32)(mb), _p = (u32)(par), _d; \
    asm volatile("{ .reg .pred p; mbarrier.try_wait.parity.acquire.cta.shared::cta.b64 p, [%1], %2; selp.b32 %0, 1, 0, p; }" \
                 : "=r"(_d) : "r"(_m), "r"(_p) : "memory"); \
    if (!_d) { \
        asm volatile("{ .reg .pred P1; WL_%=: mbarrier.try_wait.parity.acquire.cta.shared::cta.b64 P1, [%0], %1, 0x989680; @P1 bra.uni WD_%=; bra.uni WL_%=; WD_%=: }" \
                     :: "r"(_m), "r"(_p) : "memory"); \
    } \
} while (0)
#define BAR_CHAIN()   asm volatile("bar.sync 1, 256;" ::: "memory")
#define BAR3_SYNC()   asm volatile("bar.sync 3, 768;" ::: "memory")
#define BAR3_ARRIVE() asm volatile("bar.arrive 3, 768;" ::: "memory")
#define BAR4_SYNC()   asm volatile("bar.sync 4, 768;" ::: "memory")
#define BAR4_ARRIVE() asm volatile("bar.arrive 4, 768;" ::: "memory")

// ============================ prep kernels (3) ==============================
__global__ void prep_base(const float* __restrict__ W1, const float* __restrict__ W5,
                          const int* __restrict__ e_data, const float* __restrict__ q_matrix)
{
    for (int idx = blockIdx.x*blockDim.x + threadIdx.x; idx < 32896;
         idx += gridDim.x*blockDim.x) {
        if (idx < 32768) {
            int f = idx >> 8, k = idx & 255;
            g_W5T[idx] = W5[k*128 + f];
        } else {
            int f = idx - 32768;
            float s = 0.f;
            for (int k = 0; k < 128; k++) s += W1[(256+k)*128 + f];
            g_w1s[f] = s;
        }
    }
    int lane = threadIdx.x & 31;
    int gw = (blockIdx.x*blockDim.x + threadIdx.x) >> 5;
    int nw = (gridDim.x*blockDim.x) >> 5;
    for (int item = gw; item < NB*NS; item += nw) {
        const float* q = q_matrix + (long)e_data[item]*NQ;
        float s = 0.f;
        for (int i = lane; i < NQ; i += 32) s += q[i];
        s += __shfl_xor_sync(0xffffffffu, s, 16);
        s += __shfl_xor_sync(0xffffffffu, s, 8);
        s += __shfl_xor_sync(0xffffffffu, s, 4);
        s += __shfl_xor_sync(0xffffffffu, s, 2);
        s += __shfl_xor_sync(0xffffffffu, s, 1);
        if (lane == 0) g_QS[item] = s;
    }
}

__global__ void __launch_bounds__(128) prep_ALUIT(
    const int* __restrict__ e_data, const int* __restrict__ a_data,
    const int* __restrict__ at_data, const int* __restrict__ it_data,
    const float* __restrict__ E_e, const float* __restrict__ E_at,
    const float* __restrict__ E_it,
    const float* __restrict__ W1, const float* __restrict__ b1,
    const float* __restrict__ W4, const float* __restrict__ b4)
{
    int b = blockIdx.x, s0 = blockIdx.y*8, f = threadIdx.x;
    __shared__ float se[8][128], sa[8][128], si[8][128], av[8];
    int cnt = min(8, NS - s0);
    for (int t = 0; t < 8; t++) {
        if (t < cnt) {
            int s = s0 + t;
            se[t][f] = E_e [e_data [b*NS + s]*128 + f];
            sa[t][f] = E_at[at_data[b*NS + s]*128 + f];
            si[t][f] = E_it[it_data[b*NS + s]*128 + f];
            if (f == 0) av[t] = (float)a_data[b*NS + s];
        } else { se[t][f] = 0.f; sa[t][f] = 0.f; si[t][f] = 0.f; if (f == 0) av[t] = 0.f; }
    }
    __syncthreads();
    float w1sf = g_w1s[f], b1f = b1[f], b4f = b4[f];
    float acc[8], acu[8];
#pragma unroll
    for (int t = 0; t < 8; t++) { acc[t] = b1f + av[t]*w1sf; acu[t] = b4f; }
    for (int k = 0; k < 128; k++) {
        float w = W1[k*128 + f];
#pragma unroll
        for (int t = 0; t < 8; t++) acc[t] += se[t][k]*w;
    }
    for (int k = 0; k < 128; k++) {
        float w = W1[(128+k)*128 + f];
#pragma unroll
        for (int t = 0; t < 8; t++) acc[t] += sa[t][k]*w;
    }
    for (int k = 0; k < 128; k++) {
        float w = W4[(256+k)*128 + f];
#pragma unroll
        for (int t = 0; t < 8; t++) acu[t] += si[t][k]*w;
    }
    for (int t = 0; t < cnt; t++) {
        g_AL [(b*NS + s0 + t)*128 + f] = acc[t];
        g_UIT[(b*NS + s0 + t)*128 + f] = acu[t];
    }
}

__global__ void __launch_bounds__(256) prep_G23(
    const int* __restrict__ it_data, const float* __restrict__ E_it,
    const float* __restrict__ W2, const float* __restrict__ b2,
    const float* __restrict__ W3, const float* __restrict__ b3)
{
    int b = blockIdx.x, t0 = blockIdx.y*10;
    int T = min(10, 99 - t0);
    __shared__ float sf[10][384];
    for (int idx = threadIdx.x; idx < T*384; idx += 256) {
        int tt = idx / 384, kk = idx - tt*384;
        int t = t0 + tt;
        float v;
        if (kk < 128)       v = (t == 0) ? 0.f : g_AL[(b*NS + t - 1)*128 + kk];
        else if (kk < 256) { int it = it_data[b*NS + t]; v = E_it[it*128 + (kk-128)]; }
        else                v = g_AL[(b*NS + t)*128 + (kk-256)];
        sf[tt][kk] = v;
    }
    __syncthreads();
    int j = threadIdx.x;
    const float* Wc;
    float bias;
    if (j < 128) { Wc = W2 + j;        bias = b2[j];     }
    else         { Wc = W3 + (j-128);  bias = b3[j-128]; }
    float acc[10];
#pragma unroll
    for (int tt = 0; tt < 10; tt++) acc[tt] = bias;
    for (int k = 0; k < 384; k++) {
        float wv = Wc[k*128];
#pragma unroll
        for (int tt = 0; tt < 10; tt++) acc[tt] += sf[tt][k]*wv;
    }
    for (int tt = 0; tt < T; tt++) g_G23[(b*NS + t0 + tt)*256 + j] = acc[tt];
}

// ============================ main scan =====================================
// 2-CTA cluster per b, 768 threads. Warps 0..15: GEMM (4 rows x 128 cols
// each -> 4 GEMM warps per SMSP for latency hiding). Warps 16..23: chain.
#define OFF_SH     0        // 8192
#define OFF_SH128  8192     // 128
#define OFF_W4H    8320     // 16384 (k-pair interleaved)
#define OFF_W4L    24704    // 16384 [k][f]
#define OFF_LG     41088    // 128
#define OFF_C      41216    // 128
#define OFF_HT     41344    // 128
#define OFF_Q      41472    // 264
#define OFF_PART   41736    // 16*128 = 2048
#define OFF_CP     43784    // 256
#define OFF_GP     44040    // 256
#define OFF_G2P    44296    // 256
#define OFF_G3P    44552    // 256
#define OFF_PHT    44808    // 128
#define OFF_MBAR   44936    // u64 mbar (179744 B, 8-aligned)
#define SMEM_FLOATS 44940   // 179,760 B

__global__ void __launch_bounds__(768, 1) __cluster_dims__(2, 1, 1) lpkt_main(
    const int* __restrict__ e_data, const float* __restrict__ q_matrix,
    const float* __restrict__ h0, const float* __restrict__ W4,
    const float* __restrict__ W2, const float* __restrict__ W3)
{
    extern __shared__ float sm[];
    float* sh    = sm + OFF_SH;
    float* sh128 = sm + OFF_SH128;
    float* sW4h  = sm + OFF_W4H;
    float* sW4l  = sm + OFF_W4L;
    float* sLG   = sm + OFF_LG;
    float* sC    = sm + OFF_C;
    float* sHT   = sm + OFF_HT;
    float* sQ    = sm + OFF_Q;
    float* sPart = sm + OFF_PART;
    float* sCp   = sm + OFF_CP;
    float* sGp   = sm + OFF_GP;
    float* sG2p  = sm + OFF_G2P;
    float* sG3p  = sm + OFF_G3P;
    float* pHT   = sm + OFF_PHT;

    u32 rank;
    asm("mov.u32 %0, %%cluster_ctarank;" : "=r"(rank));
    const u32 peer = rank ^ 1u;
    const int b = blockIdx.x >> 1;
    const int tid = threadIdx.x;
    const int w = tid >> 5, lane = tid & 31;

    const u32 sb   = smem_u32(sm);
    const u32 mbT  = sb + OFF_MBAR*4;
    const u32 rmbT = mapa_u32(mbT, peer);
    const u32 rPHT = mapa_u32(sb + OFF_PHT*4, peer);

    // ---- init ----
    for (int idx = tid; idx < 16384; idx += 768) {
        int k = idx >> 7, c = idx & 127;
        sW4h[(k >> 1)*256 + 2*c + (k & 1)] = W4[idx];   // k-pair interleave
        sW4l[idx] = W4[16384 + idx];
    }
    for (int idx = tid; idx < 8192; idx += 768) sh[idx] = h0[rank*8192 + idx];
    if (tid < 128) sh128[tid] = h0[16384 + tid];
    if (tid < NQ) sQ[tid] = q_matrix[(long)e_data[b*NS]*NQ + tid];
    if (tid == 0) MBARRIER_INIT(mbT, 1);
    __syncthreads();
    CLUSTER_SYNC();

    // ---- ht0 ----
    if (tid < 512) {
        int f = tid & 127, qtr = tid >> 7;
        float acc = 0.f;
        for (int rr = 0; rr < 16; rr++) {
            int rl = qtr*16 + rr;
            acc += sQ[rank*64 + rl]*sh[rl*128 + f];
        }
        sPart[tid] = acc;
    }
    __syncthreads();
    float own0 = 0.f;
    if (tid < 128) {
        own0 = sPart[tid] + sPart[128+tid] + sPart[256+tid] + sPart[384+tid];
        st_cluster_f32(rPHT + tid*4, own0);
    }
    CLUSTER_SYNC();
    if (tid < 128)
        sHT[tid] = __fdividef(own0 + pHT[tid] + sQ[128]*sh128[tid], g_QS[b*NS]);
    __syncthreads();

    const int rbase = (w & 15)*4;

    for (int t = 0; t < 99; t++) {
        const float* sQE = sQ + (t & 1)*132;
        float*       sQN = sQ + ((t + 1) & 1)*132;

        if (w < 16) {
            // ================= GEMM warps (4 rows x 128 cols) =================
            u64 acc[4][4];
#pragma unroll
            for (int j = 0; j < 4; j++) {
                acc[j][0] = 0ull; acc[j][1] = 0ull; acc[j][2] = 0ull; acc[j][3] = 0ull;
            }
            const ulonglong2* Wq = (const ulonglong2*)sW4h;
            const ulonglong2* Hq = (const ulonglong2*)sh;
#pragma unroll 4
            for (int k4 = 0; k4 < 32; k4++) {
                ulonglong2 wA0 = Wq[(2*k4    )*64 + lane];
                ulonglong2 wB0 = Wq[(2*k4    )*64 + 32 + lane];
                ulonglong2 wA1 = Wq[(2*k4 + 1)*64 + lane];
                ulonglong2 wB1 = Wq[(2*k4 + 1)*64 + 32 + lane];
#pragma unroll
                for (int j = 0; j < 4; j++) {
                    ulonglong2 hq = Hq[(rbase + j)*32 + k4];
                    FMA2(acc[j][0], hq.x, wA0.x);
                    FMA2(acc[j][1], hq.x, wA0.y);
                    FMA2(acc[j][2], hq.x, wB0.x);
                    FMA2(acc[j][3], hq.x, wB0.y);
                    FMA2(acc[j][0], hq.y, wA1.x);
                    FMA2(acc[j][1], hq.y, wA1.y);
                    FMA2(acc[j][2], hq.y, wB1.x);
                    FMA2(acc[j][3], hq.y, wB1.y);
                }
            }
            BAR3_SYNC();                       // wait: sLG/sC/sQN ready

            float2 lg0 = ((const float2*)sLG)[lane];
            float2 lg1 = ((const float2*)sLG)[32 + lane];
            float2 c0  = ((const float2*)sC)[lane];
            float2 c1  = ((const float2*)sC)[32 + lane];
            float htp0 = 0.f, htp1 = 0.f, htp2 = 0.f, htp3 = 0.f;
#pragma unroll
            for (int j = 0; j < 4; j++) {
                int rl = rbase + j;
                int rg = rank*64 + rl;
                float2 a0 = unpk(acc[j][0]);
                float2 a1 = unpk(acc[j][1]);
                float2 a2 = unpk(acc[j][2]);
                float2 a3 = unpk(acc[j][3]);
                float g0 = a0.x + a0.y + c0.x;
                float g1 = a1.x + a1.y + c0.y;
                float g2 = a2.x + a2.y + c1.x;
                float g3 = a3.x + a3.y + c1.y;
                float qe = sQE[rg], qn = sQN[rg];
                float2 h0v = ((const float2*)(sh + rl*128))[lane];
                float2 h1v = ((const float2*)(sh + rl*128))[32 + lane];
                float2 hn0, hn1;
                hn0.x = qe*lg0.x + sigm(g0)*h0v.x;
                hn0.y = qe*lg0.y + sigm(g1)*h0v.y;
                hn1.x = qe*lg1.x + sigm(g2)*h1v.x;
                hn1.y = qe*lg1.y + sigm(g3)*h1v.y;
                ((float2*)(sh + rl*128))[lane]      = hn0;
                ((float2*)(sh + rl*128))[32 + lane] = hn1;
                htp0 += qn*hn0.x; htp1 += qn*hn0.y;
                htp2 += qn*hn1.x; htp3 += qn*hn1.y;
            }
            ((float2*)(sPart + w*128))[lane]      = make_float2(htp0, htp1);
            ((float2*)(sPart + w*128))[32 + lane] = make_float2(htp2, htp3);
            BAR4_ARRIVE();                     // sPart published; roll on
        } else {
            // ================= chain warps =================
            const int ct = tid - 512;
            if (ct == 0) MBAR_EXPECT_TX(mbT, 512);
            float ureg = 0.f;
            if (ct < 128) ureg = g_UIT[(b*NS + t)*128 + ct];
            if (ct < NQ) sQN[ct] = q_matrix[(long)e_data[b*NS + t + 1]*NQ + ct];

            // G partials: k-split halves, both W2 & W3 dots per thread
            {
                int j = ct & 127, kk0 = (ct >> 7)*64;
                const float* W2c = W2 + (384 + kk0)*128 + j;
                const float* W3c = W3 + (384 + kk0)*128 + j;
                const float* hpt = sHT + kk0;
                float a2[4] = {0.f, 0.f, 0.f, 0.f};
                float a3[4] = {0.f, 0.f, 0.f, 0.f};
#pragma unroll 8
                for (int kk = 0; kk < 64; kk++) {
                    float hv = hpt[kk];
                    a2[kk & 3] += hv*W2c[kk*128];
                    a3[kk & 3] += hv*W3c[kk*128];
                }
                sG2p[ct] = (a2[0] + a2[1]) + (a2[2] + a2[3]);
                sG3p[ct] = (a3[0] + a3[1]) + (a3[2] + a3[3]);
            }
            BAR_CHAIN();
            if (ct < 128) {
                const float* gb = g_G23 + (b*NS + t)*256;
                float g2 = sG2p[ct] + sG2p[128 + ct] + gb[ct];
                float g3 = sG3p[ct] + sG3p[128 + ct] + gb[128 + ct];
                sLG[ct] = sigm(g3) * sigm(2.f*g2);
            }
            BAR_CHAIN();

            // c = LG @ W4l ; g128 = h128 @ W4h  (k split in halves)
            {
                int f = ct & 127, half = ct >> 7;
                int k0 = half*64;
                float accc = 0.f, accg = 0.f;
#pragma unroll 16
                for (int kk = 0; kk < 64; kk++) {
                    int k = k0 + kk;
                    accc += sLG[k]*sW4l[k*128 + f];
                    accg += sh128[k]*sW4h[(k >> 1)*256 + 2*f + (k & 1)];
                }
                sCp[ct] = accc;
                sGp[ct] = accg;
            }
            BAR_CHAIN();
            float cf = 0.f, hn128 = 0.f;
            if (ct < 128) {
                cf = sCp[ct] + sCp[128 + ct] + ureg;
                sC[ct] = cf;
                float g128 = sGp[ct] + sGp[128 + ct] + cf;
                hn128 = sQE[128]*sLG[ct] + sigm(g128)*sh128[ct];
                sh128[ct] = hn128;
            }
            BAR3_ARRIVE();                     // publish sLG/sC/sQN
            BAR4_SYNC();                       // wait sPart

            float ownp = 0.f;
            if (ct < 128) {
#pragma unroll
                for (int ww = 0; ww < 16; ww++) ownp += sPart[ww*128 + ct];
                st_async_f32(rPHT + ct*4, ownp, rmbT);
            }
            MBAR_WAIT(mbT, t & 1);
            if (ct < 128) {
                float v = __fdividef(ownp + pHT[ct] + sQN[128]*hn128,
                                     g_QS[b*NS + t + 1]);
                sHT[ct] = v;
                if (rank == 0) g_HT[(b*NS + t)*128 + ct] = v;
            }
            BAR_CHAIN();                       // sHT visible for next G-GEMV
        }
    }
}

// ============================ epilogue ======================================
__global__ void __launch_bounds__(128) lpkt_epi(
    const int* __restrict__ e_data, const float* __restrict__ E_e,
    const float* __restrict__ b5, float* __restrict__ pred)
{
    int b = blockIdx.x, f = threadIdx.x;
    __shared__ float sx[256];
    __shared__ float sr[4];
    float b5f = b5[f];
    if (blockIdx.y == 0 && f == 0) pred[b*NS] = 0.f;
    for (int tt = 0; tt < 11; tt++) {
        int t = blockIdx.y*11 + tt;
        int en = e_data[b*NS + t + 1];
        __syncthreads();
        sx[f]       = E_e[en*128 + f];
        sx[128 + f] = g_HT[(b*NS + t)*128 + f];
        __syncthreads();
        float acc = b5f;
        const float4* wp = (const float4*)(g_W5T + f*256);
        const float4* xp = (const float4*)sx;
#pragma unroll 8
        for (int k4 = 0; k4 < 64; k4++) {
            float4 wv = wp[k4], xv = xp[k4];
            acc += wv.x*xv.x + wv.y*xv.y + wv.z*xv.z + wv.w*xv.w;
        }
        float v = sigm(acc);
        v += __shfl_xor_sync(0xffffffffu, v, 16);
        v += __shfl_xor_sync(0xffffffffu, v, 8);
        v += __shfl_xor_sync(0xffffffffu, v, 4);
        v += __shfl_xor_sync(0xffffffffu, v, 2);
        v += __shfl_xor_sync(0xffffffffu, v, 1);
        if ((f & 31) == 0) sr[f >> 5] = v;
        __syncthreads();
        if (f == 0) pred[b*NS + t + 1] = (sr[0] + sr[1] + sr[2] + sr[3]) * (1.f/128.f);
    }
}

// ============================ launch ========================================
extern "C" void kernel_launch(void* const* d_in, const int* in_sizes, int n_in,
                              void* d_out, int out_size)
{
    const int*   e_data   = (const int*)  d_in[0];
    const int*   a_data   = (const int*)  d_in[1];
    const int*   it_data  = (const int*)  d_in[2];
    const int*   at_data  = (const int*)  d_in[3];
    const float* q_matrix = (const float*)d_in[4];
    const float* h0       = (const float*)d_in[5];
    const float* E_e      = (const float*)d_in[6];
    const float* E_at     = (const float*)d_in[7];
    const float* E_it     = (const float*)d_in[8];
    const float* W1       = (const float*)d_in[9];
    const float* b1       = (const float*)d_in[10];
    const float* W2       = (const float*)d_in[11];
    const float* b2       = (const float*)d_in[12];
    const float* W3       = (const float*)d_in[13];
    const float* b3       = (const float*)d_in[14];
    const float* W4       = (const float*)d_in[15];
    const float* b4       = (const float*)d_in[16];
    const float* W5       = (const float*)d_in[17];
    const float* b5       = (const float*)d_in[18];
    float* pred = (float*)d_out;

    const int SMEM_MAIN = SMEM_FLOATS * 4;   // 179,760 B
    cudaFuncSetAttribute(lpkt_main, cudaFuncAttributeMaxDynamicSharedMemorySize, SMEM_MAIN);

    prep_base<<<64, 512>>>(W1, W5, e_data, q_matrix);                       // idx 0
    prep_ALUIT<<<dim3(64, 13), 128>>>(e_data, a_data, at_data, it_data,
                                      E_e, E_at, E_it, W1, b1, W4, b4);     // idx 1
    prep_G23<<<dim3(64, 10), 256>>>(it_data, E_it, W2, b2, W3, b3);         // idx 2
    lpkt_main<<<128, 768, SMEM_MAIN>>>(e_data, q_matrix, h0, W4, W2, W3);   // idx 3
    lpkt_epi<<<dim3(64, 9), 128>>>(e_data, E_e, b5, pred);                  // idx 4
}